// round 1
// baseline (speedup 1.0000x reference)
#include <cuda_runtime.h>
#include <math.h>

#define TT 20
#define CC 128
#define DM 256
#define NH 16
#define HWP 16384          // H*W
#define ZROW 132           // padded row stride (C=128 + 4)
#define SSTRIDE 2644       // padded per-sample z stride (20*132=2640 +4 for STS bank spread)
#define ASTRIDE 2112       // A per-sample stride = 16*132

// smem layout offsets (in floats)
#define OFF_Z   0
#define OFF_RS  21152      // 8*SSTRIDE
#define OFF_SC  23264      // +16*132
#define OFF_AT  25824      // +8*16*20
#define OFF_PL  28384      // +8*20*16
#define OFF_H1  30432      // +8*256
#define OFF_OB  31456      // +8*128
#define OFF_GS  32608      // +128*9
#define SMEM_FLOATS 32864
#define SMEM_BYTES (SMEM_FLOATS * 4)

__device__ float g_qk[NH * DM];
__device__ float g_R[NH * CC];
__device__ float g_vconst[2 * TT * DM];
__device__ float g_sconst[2 * TT * NH];

// ---------------------------------------------------------------------------
// Setup: fold PE + biases + Q into small per-(b,t) constants and a 16x128
// "score projector" R = (Q . k_w) . inconv_w.
// ---------------------------------------------------------------------------
__global__ void ltae_setup(const int* __restrict__ bpos,
                           const float* __restrict__ inconv_w,
                           const float* __restrict__ inconv_b,
                           const float* __restrict__ Q,
                           const float* __restrict__ k_w,
                           const float* __restrict__ k_b) {
    int tid = threadIdx.x;
    // qk[h][dm] = sum_d Q[h,d] * k_w[h*4+d, dm]
    for (int i = tid; i < NH * DM; i += 256) {
        int h = i >> 8, dm = i & 255;
        float acc = 0.f;
        #pragma unroll
        for (int d = 0; d < 4; d++) acc += Q[h * 4 + d] * k_w[(h * 4 + d) * DM + dm];
        g_qk[i] = acc;
    }
    __syncthreads();
    // R[h][c] = sum_dm qk[h,dm] * inconv_w[dm,c]
    for (int i = tid; i < NH * CC; i += 256) {
        int h = i >> 7, c = i & 127;
        float acc = 0.f;
        for (int dm = 0; dm < DM; dm++) acc += g_qk[h * DM + dm] * inconv_w[dm * CC + c];
        g_R[i] = acc;
    }
    // vconst[b][t][dm] = inconv_b[dm] + pe(b,t,dm)
    for (int i = tid; i < 2 * TT * DM; i += 256) {
        int dm = i & 255; int bt = i >> 8;
        int ii = dm & 15;                      // d_pe = 16, tiled over heads
        double ex = (double)(2 * (ii / 2)) / 16.0;
        float denom = (float)pow(1000.0, ex);
        float tab = (float)bpos[bt] / denom;
        float pe = (ii & 1) ? cosf(tab) : sinf(tab);
        g_vconst[i] = inconv_b[dm] + pe;
    }
    __syncthreads();
    // sconst[b][t][h] = Q[h,:].k_b[h-slice] + sum_dm vconst[b,t,dm]*qk[h,dm]
    for (int i = tid; i < 2 * TT * NH; i += 256) {
        int h = i & 15; int bt = i >> 4;
        float acc = 0.f;
        #pragma unroll
        for (int d = 0; d < 4; d++) acc += Q[h * 4 + d] * k_b[h * 4 + d];
        for (int dm = 0; dm < DM; dm++) acc += g_vconst[bt * DM + dm] * g_qk[h * DM + dm];
        g_sconst[i] = acc;
    }
}

// ---------------------------------------------------------------------------
// Main: one block handles 8 consecutive w positions at fixed (b,h).
// ---------------------------------------------------------------------------
__global__ void __launch_bounds__(512, 1)
ltae_main(const float* __restrict__ x,
          const float* __restrict__ in_w, const float* __restrict__ in_b,
          const float* __restrict__ inconv_w,
          const float* __restrict__ mlp_w, const float* __restrict__ mlp_b,
          const float* __restrict__ ln_w, const float* __restrict__ ln_b,
          const float* __restrict__ on_w, const float* __restrict__ on_b,
          float* __restrict__ out) {
    extern __shared__ float sm[];
    float* Z  = sm + OFF_Z;
    float* RS = sm + OFF_RS;
    float* SC = sm + OFF_SC;
    float* AT = sm + OFF_AT;
    float* PL = sm + OFF_PL;
    float* H1 = sm + OFF_H1;
    float* OB = sm + OFF_OB;
    float* GS = sm + OFF_GS;

    const int tid = threadIdx.x;
    const int blk = blockIdx.x;
    const int wblk = blk & 15;
    const int hrow = (blk >> 4) & 127;
    const int b = blk >> 11;
    const int w0 = wblk * 8;

    const float* xb = x + (size_t)b * TT * CC * HWP + (size_t)hrow * 128 + w0;

    // stage R into smem (broadcast-friendly)
    for (int i = tid; i < NH * CC; i += 512) {
        int h = i >> 7, c = i & 127;
        RS[h * ZROW + c] = g_R[i];
    }

    // ---- Phase 1: load x tile (coalesced in w), GroupNorm stats, normalize
    const int s = tid & 7;
    const int lane64 = tid >> 3;
    for (int k = 0; k < 40; k++) {
        int pair = lane64 + (k << 6);        // 0..2559 = t*128 + c
        int t = pair >> 7, c = pair & 127;
        Z[s * SSTRIDE + t * ZROW + c] = xb[((size_t)(t * CC + c)) * HWP + s];
    }
    __syncthreads();

    if (tid < 128) {
        int ss = tid >> 4, g = tid & 15;
        float sum = 0.f, sq = 0.f;
        const float* zp = Z + ss * SSTRIDE + g * 8;
        #pragma unroll
        for (int t = 0; t < TT; t++) {
            #pragma unroll
            for (int j = 0; j < 8; j++) {
                float v = zp[t * ZROW + j];
                sum += v; sq += v * v;
            }
        }
        float mu = sum * (1.f / 160.f);
        float var = sq * (1.f / 160.f) - mu * mu;
        GS[tid * 2]     = mu;
        GS[tid * 2 + 1] = rsqrtf(var + 1e-5f);
    }
    __syncthreads();

    for (int k = 0; k < 40; k++) {
        int pair = lane64 + (k << 6);
        int t = pair >> 7, c = pair & 127;
        int g = c >> 3;
        float mu  = GS[(s * 16 + g) * 2];
        float inv = GS[(s * 16 + g) * 2 + 1];
        int idx = s * SSTRIDE + t * ZROW + c;
        Z[idx] = (Z[idx] - mu) * inv * in_w[c] + in_b[c];
    }
    __syncthreads();

    // ---- Phase 2: scores[s,h,t] = 0.5*( z[s,t,:].R[h,:] + sconst[b,t,h] )
    if (tid < 320) {
        int hh = tid & 1;               // head half
        int rem = tid >> 1;             // 0..159
        int t = rem % 20;
        int ss = rem / 20;
        const float4* zr = (const float4*)(Z + ss * SSTRIDE + t * ZROW);
        float acc[8] = {0.f, 0.f, 0.f, 0.f, 0.f, 0.f, 0.f, 0.f};
        #pragma unroll
        for (int c4 = 0; c4 < 32; c4++) {
            float4 zq = zr[c4];
            #pragma unroll
            for (int j = 0; j < 8; j++) {
                const float4 rq = *(const float4*)(RS + (hh * 8 + j) * ZROW + c4 * 4);
                acc[j] += zq.x * rq.x + zq.y * rq.y + zq.z * rq.z + zq.w * rq.w;
            }
        }
        #pragma unroll
        for (int j = 0; j < 8; j++) {
            int h = hh * 8 + j;
            SC[ss * 320 + h * 20 + t] =
                (acc[j] + g_sconst[(b * TT + t) * NH + h]) * 0.5f;
        }
    }
    __syncthreads();

    // ---- Phase 3: softmax over t, store transposed attn [s][t][h]
    if (tid < 128) {
        int ss = tid >> 4, h = tid & 15;
        const float* sp = SC + ss * 320 + h * 20;
        float m = -1e30f;
        #pragma unroll
        for (int t = 0; t < TT; t++) m = fmaxf(m, sp[t]);
        float e[TT]; float sumv = 0.f;
        #pragma unroll
        for (int t = 0; t < TT; t++) { e[t] = expf(sp[t] - m); sumv += e[t]; }
        float r = 1.f / sumv;
        #pragma unroll
        for (int t = 0; t < TT; t++) AT[ss * 320 + t * 16 + h] = e[t] * r;
    }
    __syncthreads();

    // ---- Phase 4: A[s,h,c] = sum_t attn[s,h,t] * z[s,t,c] (regs), overlay into Z
    {
        int ss = tid >> 6;
        int cl = tid & 63;              // handles c = 2*cl, 2*cl+1
        float aA[16], aB[16];
        #pragma unroll
        for (int j = 0; j < 16; j++) { aA[j] = 0.f; aB[j] = 0.f; }
        const float* zp = Z + ss * SSTRIDE + cl * 2;
        const float* ap = AT + ss * 320;
        #pragma unroll
        for (int t = 0; t < TT; t++) {
            float2 zz = *(const float2*)(zp + t * ZROW);
            const float4* aq4 = (const float4*)(ap + t * 16);
            float4 q0 = aq4[0], q1 = aq4[1], q2 = aq4[2], q3 = aq4[3];
            float av[16] = {q0.x, q0.y, q0.z, q0.w, q1.x, q1.y, q1.z, q1.w,
                            q2.x, q2.y, q2.z, q2.w, q3.x, q3.y, q3.z, q3.w};
            #pragma unroll
            for (int j = 0; j < 16; j++) {
                aA[j] += av[j] * zz.x;
                aB[j] += av[j] * zz.y;
            }
        }
        __syncthreads();                 // all z reads done before overwrite
        #pragma unroll
        for (int j = 0; j < 16; j++) {
            float2 w2; w2.x = aA[j]; w2.y = aB[j];
            *(float2*)(Z + ss * ASTRIDE + j * ZROW + cl * 2) = w2;
        }
    }
    __syncthreads();

    // ---- Phase 5: pooled[s,d] = sum_c A[s,h(d),c]*inconv_w[d,c] + sum_t attn*vconst
    {
        int d = tid & 255;
        int sh = tid >> 8;               // 0..1 -> samples sh*4..sh*4+3
        int h = d >> 4;
        float acc[4] = {0.f, 0.f, 0.f, 0.f};
        const float4* wrow = (const float4*)(inconv_w + d * CC);
        #pragma unroll 8
        for (int c4 = 0; c4 < 32; c4++) {
            float4 wq = __ldg(wrow + c4);
            #pragma unroll
            for (int j = 0; j < 4; j++) {
                int ss = sh * 4 + j;
                const float4 aq = *(const float4*)(Z + ss * ASTRIDE + h * ZROW + c4 * 4);
                acc[j] += wq.x * aq.x + wq.y * aq.y + wq.z * aq.z + wq.w * aq.w;
            }
        }
        const float* vc = g_vconst + (b * TT) * DM + d;
        #pragma unroll
        for (int t = 0; t < TT; t++) {
            float v = __ldg(vc + t * DM);
            #pragma unroll
            for (int j = 0; j < 4; j++)
                acc[j] += AT[(sh * 4 + j) * 320 + t * 16 + h] * v;
        }
        #pragma unroll
        for (int j = 0; j < 4; j++) PL[(sh * 4 + j) * 256 + d] = acc[j];
    }
    __syncthreads();

    // ---- Phase 6: MLP h1[s,o] = pooled[s,:].mlp_w[o,:] + mlp_b[o]
    if (tid < 128) {
        int o = tid;
        float acc[8] = {0.f, 0.f, 0.f, 0.f, 0.f, 0.f, 0.f, 0.f};
        const float4* wr = (const float4*)(mlp_w + o * DM);
        #pragma unroll 8
        for (int d4 = 0; d4 < 64; d4++) {
            float4 wq = __ldg(wr + d4);
            #pragma unroll
            for (int ss = 0; ss < 8; ss++) {
                const float4 pq = *(const float4*)(PL + ss * 256 + d4 * 4);
                acc[ss] += wq.x * pq.x + wq.y * pq.y + wq.z * pq.z + wq.w * pq.w;
            }
        }
        float bo = mlp_b[o];
        #pragma unroll
        for (int ss = 0; ss < 8; ss++) H1[ss * 128 + o] = acc[ss] + bo;
    }
    __syncthreads();

    // ---- Phase 7: LayerNorm + exact GELU + GroupNorm(16) + transpose to OB
    if (tid < 256) {
        int ss = tid >> 5, lane = tid & 31;     // lane owns o = 4*lane..4*lane+3
        float4 v = *(const float4*)(H1 + ss * 128 + lane * 4);
        float smv = v.x + v.y + v.z + v.w;
        float sqv = v.x * v.x + v.y * v.y + v.z * v.z + v.w * v.w;
        #pragma unroll
        for (int off = 16; off; off >>= 1) {
            smv += __shfl_xor_sync(0xffffffffu, smv, off);
            sqv += __shfl_xor_sync(0xffffffffu, sqv, off);
        }
        float mu = smv * (1.f / 128.f);
        float inv = rsqrtf(sqv * (1.f / 128.f) - mu * mu + 1e-5f);
        float g[4]; float vv[4] = {v.x, v.y, v.z, v.w};
        #pragma unroll
        for (int j = 0; j < 4; j++) {
            int o = lane * 4 + j;
            float u = (vv[j] - mu) * inv * ln_w[o] + ln_b[o];
            g[j] = 0.5f * u * (1.f + erff(u * 0.70710678118654752f));
        }
        float s4 = g[0] + g[1] + g[2] + g[3];
        float q4 = g[0] * g[0] + g[1] * g[1] + g[2] * g[2] + g[3] * g[3];
        float s8 = s4 + __shfl_xor_sync(0xffffffffu, s4, 1);
        float q8 = q4 + __shfl_xor_sync(0xffffffffu, q4, 1);
        float mu2 = s8 * 0.125f;
        float inv2 = rsqrtf(q8 * 0.125f - mu2 * mu2 + 1e-5f);
        #pragma unroll
        for (int j = 0; j < 4; j++) {
            int o = lane * 4 + j;
            OB[o * 9 + ss] = (g[j] - mu2) * inv2 * on_w[o] + on_b[o];
        }
    }
    __syncthreads();

    // ---- coalesced store: out[b, o, hrow, w0+sw]
    #pragma unroll
    for (int k = tid; k < 1024; k += 512) {
        int o = k >> 3, sw = k & 7;
        out[(((size_t)(b * 128 + o)) << 14) + hrow * 128 + w0 + sw] = OB[o * 9 + sw];
    }
}

// ---------------------------------------------------------------------------
extern "C" void kernel_launch(void* const* d_in, const int* in_sizes, int n_in,
                              void* d_out, int out_size) {
    const float* x        = (const float*)d_in[0];
    const int*   bpos     = (const int*)  d_in[1];
    const float* in_w     = (const float*)d_in[2];
    const float* in_b     = (const float*)d_in[3];
    const float* inconv_w = (const float*)d_in[4];
    const float* inconv_b = (const float*)d_in[5];
    const float* Q        = (const float*)d_in[6];
    const float* k_w      = (const float*)d_in[7];
    const float* k_b      = (const float*)d_in[8];
    const float* mlp_w    = (const float*)d_in[9];
    const float* mlp_b    = (const float*)d_in[10];
    const float* ln_w     = (const float*)d_in[11];
    const float* ln_b     = (const float*)d_in[12];
    const float* on_w     = (const float*)d_in[13];
    const float* on_b     = (const float*)d_in[14];
    float* out = (float*)d_out;

    cudaFuncSetAttribute(ltae_main, cudaFuncAttributeMaxDynamicSharedMemorySize,
                         SMEM_BYTES);

    ltae_setup<<<1, 256>>>(bpos, inconv_w, inconv_b, Q, k_w, k_b);
    ltae_main<<<4096, 512, SMEM_BYTES>>>(x, in_w, in_b, inconv_w,
                                         mlp_w, mlp_b, ln_w, ln_b,
                                         on_w, on_b, out);
}